// round 5
// baseline (speedup 1.0000x reference)
#include <cuda_runtime.h>
#include <cuda_bf16.h>
#include <cstdint>

// Problem dims (fixed)
#define BATCH 256
#define TSEQ  512
#define DDIM  128
#define ND3   384   // 3*D
#define ROW3  98304 // BATCH*ND3  (one timestep row of xp)
#define TD    65536 // TSEQ*DDIM  (one sample of states)

// ---------------- scratch (static device arrays; no allocations) ----------------
__device__ float g_xpa[(size_t)TSEQ * BATCH * ND3]; // [t][b][3D] input proj, GRU a
__device__ float g_xpb[(size_t)TSEQ * BATCH * ND3]; // [t][b][3D] input proj, GRU b
__device__ float g_g[(size_t)BATCH * TSEQ * DDIM];  // GRU a states [b][t][d]
__device__ float g_h[(size_t)BATCH * TSEQ * DDIM];  // GRU b states [b][t][d]

typedef unsigned long long ull;

__device__ __forceinline__ void ffma2(ull &d, ull a, ull b) {
    asm("fma.rn.f32x2 %0, %1, %2, %0;" : "+l"(d) : "l"(a), "l"(b));
}
__device__ __forceinline__ ull pk2(float lo, float hi) {
    ull r; asm("mov.b64 %0, {%1,%2};" : "=l"(r) : "f"(lo), "f"(hi)); return r;
}
__device__ __forceinline__ float2 upk2(ull v) {
    float lo, hi; asm("mov.b64 {%0,%1}, %2;" : "=f"(lo), "=f"(hi) : "l"(v));
    return make_float2(lo, hi);
}
__device__ __forceinline__ float sigm(float v) { return 1.f / (1.f + __expf(-v)); }

// ============================================================================
// Kernel 1: xp[t][b][c] = rx[b][t] @ W + b_in,  rx = per-sample reversed x.
// 64x64 output tile, K=128 in two 64-chunks, f32x2 k-paired accumulation.
// grid (2048, 6, 2): x -> (b, t-tile), y -> col tile, z -> {Wa,ba}->xpa / {Wb,bb}->xpb
// ============================================================================
__global__ void __launch_bounds__(256) k_xp(
    const float* __restrict__ x, const int* __restrict__ lengths,
    const float* __restrict__ Wa, const float* __restrict__ ba,
    const float* __restrict__ Wb, const float* __restrict__ bb)
{
    __shared__ __align__(16) float As[64][64];
    __shared__ __align__(8)  float2 Bs2[32][66]; // k-paired: Bs2[kp][c] = {W[2kp][c], W[2kp+1][c]}

    const int z = blockIdx.z;
    const float* W    = z ? Wb : Wa;
    const float* bias = z ? bb : ba;
    float* xp         = z ? g_xpb : g_xpa;

    const int rt  = blockIdx.x;
    const int b   = rt >> 3;
    const int t0  = (rt & 7) << 6;
    const int c0  = blockIdx.y << 6;
    const int len = lengths[b];
    const int tid = threadIdx.x;
    const int tx  = tid & 15, ty = tid >> 4;

    ull acc[4][4];
#pragma unroll
    for (int i = 0; i < 4; i++)
#pragma unroll
        for (int j = 0; j < 4; j++) acc[i][j] = 0ull;

    for (int kc = 0; kc < 2; ++kc) {
        __syncthreads();
        // load A chunk: 64 rows (t) x 64 k (reversed, masked)
#pragma unroll
        for (int l = 0; l < 16; ++l) {
            int idx = tid + l * 256;
            int i = idx >> 6, kk = idx & 63;
            int t = t0 + i;
            float v = 0.f;
            if (t < len)
                v = x[((size_t)b * TSEQ + (len - 1 - t)) * DDIM + kc * 64 + kk];
            As[i][kk] = v;
        }
        // load B chunk k-paired: 64 k x 64 c
#pragma unroll
        for (int l = 0; l < 16; ++l) {
            int idx = tid + l * 256;
            int kk = idx >> 6, jj = idx & 63;
            float w = W[(size_t)(kc * 64 + kk) * ND3 + c0 + jj];
            ((float*)&Bs2[kk >> 1][jj])[kk & 1] = w;
        }
        __syncthreads();
#pragma unroll
        for (int q = 0; q < 16; ++q) {
            ulonglong2 av[4];
#pragma unroll
            for (int i = 0; i < 4; i++)
                av[i] = *(const ulonglong2*)&As[4 * ty + i][4 * q];
            ull bv0[4], bv1[4];
#pragma unroll
            for (int j = 0; j < 4; j++) {
                bv0[j] = *(const ull*)&Bs2[2 * q    ][4 * tx + j];
                bv1[j] = *(const ull*)&Bs2[2 * q + 1][4 * tx + j];
            }
#pragma unroll
            for (int i = 0; i < 4; i++)
#pragma unroll
                for (int j = 0; j < 4; j++) {
                    ffma2(acc[i][j], av[i].x, bv0[j]);
                    ffma2(acc[i][j], av[i].y, bv1[j]);
                }
        }
    }
#pragma unroll
    for (int i = 0; i < 4; i++) {
        int t = t0 + 4 * ty + i;
#pragma unroll
        for (int j = 0; j < 4; j++) {
            int c = c0 + 4 * tx + j;
            float2 f = upk2(acc[i][j]);
            xp[(size_t)t * ROW3 + (size_t)b * ND3 + c] = f.x + f.y + bias[c];
        }
    }
}

// ============================================================================
// Kernel 2: masked GRU recurrence. grid 128 blocks = 2 GRUs x 64 chunks (4 samples).
// 384 threads; thread j owns U column j as 64 f32x2 register pairs.
// h[4][128] lives in smem; per step: rp = h@U + b_rec (FMA2), then gates.
// ============================================================================
__global__ void __launch_bounds__(384, 1) k_gru(
    const int*   __restrict__ lengths,
    const float* __restrict__ Ua, const float* __restrict__ ba_rec,
    const float* __restrict__ Ub, const float* __restrict__ bb_rec)
{
    __shared__ __align__(16) float hsm[4][DDIM];
    __shared__ float rps[4][ND3];

    const int gru   = blockIdx.x >> 6;
    const int chunk = blockIdx.x & 63;
    const int b0    = chunk * 4;
    const int j     = threadIdx.x;

    const float* U   = gru ? Ub     : Ua;
    const float* brp = gru ? bb_rec : ba_rec;
    const float* xp  = gru ? g_xpb  : g_xpa;
    float*       st  = gru ? g_h    : g_g;

    int len_s[4];
#pragma unroll
    for (int s = 0; s < 4; s++) len_s[s] = lengths[b0 + s];
    int maxlen = max(max(len_s[0], len_s[1]), max(len_s[2], len_s[3]));

    ull u2[64];
#pragma unroll
    for (int kp = 0; kp < 64; ++kp)
        u2[kp] = pk2(U[(size_t)(2 * kp) * ND3 + j], U[(size_t)(2 * kp + 1) * ND3 + j]);
    const float brec = brp[j];

    for (int idx = j; idx < 4 * DDIM; idx += 384) ((float*)hsm)[idx] = 0.f;
    __syncthreads();

    const int s1 = j >> 7, d1 = j & 127;

    for (int t = 0; t < maxlen; ++t) {
        // prefetch xp for this thread's gate pair(s)
        const float* xpt = xp + (size_t)t * ROW3 + (size_t)b0 * ND3;
        float xz1 = xpt[s1 * ND3 +       d1];
        float xr1 = xpt[s1 * ND3 + 128 + d1];
        float xh1 = xpt[s1 * ND3 + 256 + d1];
        float xz2 = 0.f, xr2 = 0.f, xh2 = 0.f;
        if (j < 128) {
            xz2 = xpt[3 * ND3 +       j];
            xr2 = xpt[3 * ND3 + 128 + j];
            xh2 = xpt[3 * ND3 + 256 + j];
        }
        // rp[s][j] = sum_k h[s][k] * U[k][j] + b_rec[j]
        ull acc[4];
#pragma unroll
        for (int s = 0; s < 4; s++) acc[s] = pk2(brec, 0.f);
#pragma unroll
        for (int q = 0; q < 32; ++q) {
            ull u0 = u2[2 * q], u1 = u2[2 * q + 1];
#pragma unroll
            for (int s = 0; s < 4; s++) {
                ulonglong2 hv = *(const ulonglong2*)&hsm[s][4 * q];
                ffma2(acc[s], u0, hv.x);
                ffma2(acc[s], u1, hv.y);
            }
        }
#pragma unroll
        for (int s = 0; s < 4; s++) { float2 f = upk2(acc[s]); rps[s][j] = f.x + f.y; }
        __syncthreads();
        // gates: pair 1 (s1,d1) for all threads; pair 2 (3, j) for j<128
        {
            float h_old = hsm[s1][d1];
            float hn = h_old;
            if (t < len_s[s1]) {
                float zg = sigm(xz1 + rps[s1][d1]);
                float rg = sigm(xr1 + rps[s1][128 + d1]);
                float hh = tanhf(xh1 + rg * rps[s1][256 + d1]);
                hn = zg * h_old + (1.f - zg) * hh;
            }
            hsm[s1][d1] = hn;
            st[(size_t)(b0 + s1) * TD + (size_t)t * DDIM + d1] = hn;
        }
        if (j < 128) {
            float h_old = hsm[3][j];
            float hn = h_old;
            if (t < len_s[3]) {
                float zg = sigm(xz2 + rps[3][j]);
                float rg = sigm(xr2 + rps[3][128 + j]);
                float hh = tanhf(xh2 + rg * rps[3][256 + j]);
                hn = zg * h_old + (1.f - zg) * hh;
            }
            hsm[3][j] = hn;
            st[(size_t)(b0 + 3) * TD + (size_t)t * DDIM + j] = hn;
        }
        __syncthreads();
    }
    // tail fill: t in [maxlen, T): state carries forward
    const int tail = TSEQ - maxlen;
    for (int idx = j; idx < tail * 512; idx += 384) {
        int d  = idx & 127;
        int s  = (idx >> 7) & 3;
        int tt = idx >> 9;
        st[(size_t)(b0 + s) * TD + (size_t)(maxlen + tt) * DDIM + d] = hsm[s][d];
    }
}

// ============================================================================
// Kernel 3: fused attention epilogue, one block per batch sample (128 threads).
// e = g@W_alpha + b_alpha -> softmax over t; out[d] = sum_t alpha_t *
//   tanh(h[t]@W_beta[:,d] + b_beta[d]) * x[b][t][d].
// ============================================================================
__global__ void __launch_bounds__(128, 2) k_attn(
    const float* __restrict__ x,
    const float* __restrict__ W_alpha, const float* __restrict__ b_alpha,
    const float* __restrict__ W_beta,  const float* __restrict__ b_beta,
    float* __restrict__ out)
{
    __shared__ float e_s[TSEQ];
    __shared__ float red[4];
    __shared__ float scal[2];
    __shared__ __align__(16) float hwin[8][DDIM];
    __shared__ float xwin[8][DDIM];

    const int b    = blockIdx.x;
    const int tid  = threadIdx.x;
    const int lane = tid & 31, w = tid >> 5;

    // ---- phase 1: e[t] = g[b][t] . W_alpha + b_alpha (warp per t) ----
    float4 wa = *(const float4*)&W_alpha[lane * 4];
    const float b_a = b_alpha[0];
    const float* gbase = g_g + (size_t)b * TD;
    for (int tt = 0; tt < 128; ++tt) {
        int t = tt * 4 + w;
        float4 gv = *(const float4*)&gbase[(size_t)t * DDIM + lane * 4];
        float sum = gv.x * wa.x + gv.y * wa.y + gv.z * wa.z + gv.w * wa.w;
#pragma unroll
        for (int o = 16; o > 0; o >>= 1) sum += __shfl_xor_sync(0xffffffffu, sum, o);
        if (lane == 0) e_s[t] = sum + b_a;
    }
    __syncthreads();

    // ---- softmax over t (store unnormalized exp; divide once at the end) ----
    float m = -1e30f;
    for (int i = tid; i < TSEQ; i += 128) m = fmaxf(m, e_s[i]);
#pragma unroll
    for (int o = 16; o > 0; o >>= 1) m = fmaxf(m, __shfl_xor_sync(0xffffffffu, m, o));
    if (lane == 0) red[w] = m;
    __syncthreads();
    if (tid == 0) scal[0] = fmaxf(fmaxf(red[0], red[1]), fmaxf(red[2], red[3]));
    __syncthreads();
    const float M = scal[0];
    float ss = 0.f;
    for (int i = tid; i < TSEQ; i += 128) { float p = __expf(e_s[i] - M); e_s[i] = p; ss += p; }
#pragma unroll
    for (int o = 16; o > 0; o >>= 1) ss += __shfl_xor_sync(0xffffffffu, ss, o);
    if (lane == 0) red[w] = ss;
    __syncthreads();
    if (tid == 0) scal[1] = red[0] + red[1] + red[2] + red[3];
    __syncthreads();
    const float Sinv = 1.f / scal[1];

    // ---- phase 2: beta GEMV with W_beta column in registers (f32x2 pairs) ----
    ull wb2[64];
#pragma unroll
    for (int kp = 0; kp < 64; ++kp)
        wb2[kp] = pk2(W_beta[(size_t)(2 * kp) * DDIM + tid],
                      W_beta[(size_t)(2 * kp + 1) * DDIM + tid]);
    const float bb = b_beta[tid];
    const float* hbase = g_h + (size_t)b * TD;
    const float* xbase = x   + (size_t)b * TD;
    float acc = 0.f;

    for (int tw = 0; tw < TSEQ; tw += 8) {
        __syncthreads();
#pragma unroll
        for (int l = 0; l < 8; ++l) {
            int idx = tid + l * 128;
            int tt = idx >> 7, k = idx & 127;
            hwin[tt][k] = hbase[(size_t)(tw + tt) * DDIM + k];
            xwin[tt][k] = xbase[(size_t)(tw + tt) * DDIM + k];
        }
        __syncthreads();
#pragma unroll
        for (int tt = 0; tt < 8; ++tt) {
            ull a2 = 0ull;
#pragma unroll
            for (int q = 0; q < 32; ++q) {
                ulonglong2 hv = *(const ulonglong2*)&hwin[tt][4 * q];
                ffma2(a2, wb2[2 * q],     hv.x);
                ffma2(a2, wb2[2 * q + 1], hv.y);
            }
            float2 f = upk2(a2);
            float beta = tanhf(f.x + f.y + bb);
            acc += e_s[tw + tt] * beta * xwin[tt][tid];
        }
    }
    out[(size_t)b * DDIM + tid] = acc * Sinv;
}

// ============================================================================
extern "C" void kernel_launch(void* const* d_in, const int* in_sizes, int n_in,
                              void* d_out, int out_size)
{
    const float* x       = (const float*)d_in[0];
    const int*   lengths = (const int*)  d_in[1];
    const float* Wa      = (const float*)d_in[2];
    const float* Ua      = (const float*)d_in[3];
    const float* ba_in   = (const float*)d_in[4];
    const float* ba_rec  = (const float*)d_in[5];
    const float* Wb      = (const float*)d_in[6];
    const float* Ub      = (const float*)d_in[7];
    const float* bb_in   = (const float*)d_in[8];
    const float* bb_rec  = (const float*)d_in[9];
    const float* W_alpha = (const float*)d_in[10];
    const float* b_alpha = (const float*)d_in[11];
    const float* W_beta  = (const float*)d_in[12];
    const float* b_beta  = (const float*)d_in[13];
    float* out = (float*)d_out;

    k_xp  <<<dim3(2048, 6, 2), 256>>>(x, lengths, Wa, ba_in, Wb, bb_in);
    k_gru <<<128, 384>>>(lengths, Ua, ba_rec, Ub, bb_rec);
    k_attn<<<256, 128>>>(x, W_alpha, b_alpha, W_beta, b_beta, out);
    (void)in_sizes; (void)n_in; (void)out_size;
}

// round 6
// speedup vs baseline: 1.6790x; 1.6790x over previous
#include <cuda_runtime.h>
#include <cuda_bf16.h>
#include <cstdint>

// Problem dims (fixed)
#define BATCH 256
#define TSEQ  512
#define DDIM  128
#define ND3   384   // 3*D
#define ROW3  98304 // BATCH*ND3  (one timestep row of xp)
#define TD    65536 // TSEQ*DDIM  (one sample of states)

// ---------------- scratch (static device arrays; no allocations) ----------------
__device__ float g_xpa[(size_t)TSEQ * BATCH * ND3]; // [t][b][3D] input proj, GRU a
__device__ float g_xpb[(size_t)TSEQ * BATCH * ND3]; // [t][b][3D] input proj, GRU b
__device__ float g_g[(size_t)BATCH * TSEQ * DDIM];  // GRU a states [b][t][d]
__device__ float g_h[(size_t)BATCH * TSEQ * DDIM];  // GRU b states [b][t][d]
__device__ int   g_perm[BATCH];                     // descending-length permutation

typedef unsigned long long ull;

__device__ __forceinline__ void ffma2(ull &d, ull a, ull b) {
    asm("fma.rn.f32x2 %0, %1, %2, %0;" : "+l"(d) : "l"(a), "l"(b));
}
__device__ __forceinline__ ull pk2(float lo, float hi) {
    ull r; asm("mov.b64 %0, {%1,%2};" : "=l"(r) : "f"(lo), "f"(hi)); return r;
}
__device__ __forceinline__ float2 upk2(ull v) {
    float lo, hi; asm("mov.b64 {%0,%1}, %2;" : "=f"(lo), "=f"(hi) : "l"(v));
    return make_float2(lo, hi);
}
__device__ __forceinline__ float sigm(float v) { return 1.f / (1.f + __expf(-v)); }

// ============================================================================
// Kernel 0: descending rank-sort of lengths -> g_perm (O(B^2), one block)
// ============================================================================
__global__ void __launch_bounds__(BATCH) k_sort(const int* __restrict__ lengths)
{
    __shared__ int ls[BATCH];
    const int i = threadIdx.x;
    ls[i] = lengths[i];
    __syncthreads();
    const int li = ls[i];
    int r = 0;
#pragma unroll 8
    for (int j = 0; j < BATCH; ++j) {
        int lj = ls[j];
        r += (lj > li) || (lj == li && j < i);
    }
    g_perm[r] = i;
}

// ============================================================================
// Kernel 1: xp[t][b][c] = rx[b][t] @ W + b_in,  rx = per-sample reversed x.
// 64x64 output tile, K=128 in two 64-chunks, f32x2 k-paired accumulation.
// Tiles entirely past the sample's length are skipped (their xp is never used).
// grid (2048, 6, 2): x -> (b, t-tile), y -> col tile, z -> {Wa,ba} / {Wb,bb}
// ============================================================================
__global__ void __launch_bounds__(256) k_xp(
    const float* __restrict__ x, const int* __restrict__ lengths,
    const float* __restrict__ Wa, const float* __restrict__ ba,
    const float* __restrict__ Wb, const float* __restrict__ bb)
{
    const int rt  = blockIdx.x;
    const int b   = rt >> 3;
    const int t0  = (rt & 7) << 6;
    const int len = lengths[b];
    if (t0 >= len) return;   // dead tile: values never consumed downstream

    __shared__ __align__(16) float As[64][64];
    __shared__ __align__(16) float2 Bs2[32][66]; // k-paired: Bs2[kp][c]={W[2kp][c],W[2kp+1][c]}

    const int z = blockIdx.z;
    const float* W    = z ? Wb : Wa;
    const float* bias = z ? bb : ba;
    float* xp         = z ? g_xpb : g_xpa;

    const int c0  = blockIdx.y << 6;
    const int tid = threadIdx.x;
    const int tx  = tid & 15, ty = tid >> 4;

    ull acc[4][4];
#pragma unroll
    for (int i = 0; i < 4; i++)
#pragma unroll
        for (int j = 0; j < 4; j++) acc[i][j] = 0ull;

    for (int kc = 0; kc < 2; ++kc) {
        __syncthreads();
        // A chunk: 64 t-rows x 64 k (reversed, masked)
#pragma unroll
        for (int l = 0; l < 16; ++l) {
            int idx = tid + l * 256;
            int i = idx >> 6, kk = idx & 63;
            int t = t0 + i;
            float v = 0.f;
            if (t < len)
                v = x[((size_t)b * TSEQ + (len - 1 - t)) * DDIM + kc * 64 + kk];
            As[i][kk] = v;
        }
        // B chunk k-paired: 64 k x 64 c
#pragma unroll
        for (int l = 0; l < 16; ++l) {
            int idx = tid + l * 256;
            int kk = idx >> 6, jj = idx & 63;
            float w = W[(size_t)(kc * 64 + kk) * ND3 + c0 + jj];
            ((float*)&Bs2[kk >> 1][jj])[kk & 1] = w;
        }
        __syncthreads();
#pragma unroll
        for (int q = 0; q < 16; ++q) {
            ulonglong2 av[4];
#pragma unroll
            for (int i = 0; i < 4; i++)
                av[i] = *(const ulonglong2*)&As[4 * ty + i][4 * q];
            // B rows 2q, 2q+1 as LDS.128 (two ulonglong2 each)
            ulonglong2 b0a = *(const ulonglong2*)&Bs2[2 * q    ][4 * tx];
            ulonglong2 b0b = *(const ulonglong2*)&Bs2[2 * q    ][4 * tx + 2];
            ulonglong2 b1a = *(const ulonglong2*)&Bs2[2 * q + 1][4 * tx];
            ulonglong2 b1b = *(const ulonglong2*)&Bs2[2 * q + 1][4 * tx + 2];
            ull bv0[4] = { b0a.x, b0a.y, b0b.x, b0b.y };
            ull bv1[4] = { b1a.x, b1a.y, b1b.x, b1b.y };
#pragma unroll
            for (int i = 0; i < 4; i++)
#pragma unroll
                for (int j = 0; j < 4; j++) {
                    ffma2(acc[i][j], av[i].x, bv0[j]);
                    ffma2(acc[i][j], av[i].y, bv1[j]);
                }
        }
    }
#pragma unroll
    for (int i = 0; i < 4; i++) {
        int t = t0 + 4 * ty + i;
#pragma unroll
        for (int j = 0; j < 4; j++) {
            int c = c0 + 4 * tx + j;
            float2 f = upk2(acc[i][j]);
            xp[(size_t)t * ROW3 + (size_t)b * ND3 + c] = f.x + f.y + bias[c];
        }
    }
}

// ============================================================================
// Kernel 2: masked GRU recurrence, length-sorted 2-sample chunks.
// grid 256 blocks: block i -> gru = i&1, pair = i>>1 (work descends with i).
// 384 threads; thread j owns U column j as 64 f32x2 register pairs.
// ============================================================================
__global__ void __launch_bounds__(384, 1) k_gru(
    const int*   __restrict__ lengths,
    const float* __restrict__ Ua, const float* __restrict__ ba_rec,
    const float* __restrict__ Ub, const float* __restrict__ bb_rec)
{
    __shared__ __align__(16) float hsm[2][DDIM];
    __shared__ float rps[2][ND3];

    const int gru = blockIdx.x & 1;
    const int pr  = blockIdx.x >> 1;
    const int j   = threadIdx.x;

    const float* U   = gru ? Ub     : Ua;
    const float* brp = gru ? bb_rec : ba_rec;
    const float* xp  = gru ? g_xpb  : g_xpa;
    float*       st  = gru ? g_h    : g_g;

    const int b_s0 = g_perm[2 * pr];
    const int b_s1 = g_perm[2 * pr + 1];
    const int len0 = lengths[b_s0];
    const int len1 = lengths[b_s1];
    const int maxlen = max(len0, len1);

    ull u2[64];
#pragma unroll
    for (int kp = 0; kp < 64; ++kp)
        u2[kp] = pk2(U[(size_t)(2 * kp) * ND3 + j], U[(size_t)(2 * kp + 1) * ND3 + j]);
    const float brec = brp[j];

    for (int idx = j; idx < 2 * DDIM; idx += 384) ((float*)hsm)[idx] = 0.f;
    __syncthreads();

    // gate assignment: j<128 -> (sample 0, d=j); 128<=j<256 -> (sample 1, d=j-128)
    const int s  = (j >> 7) & 1;
    const int d  = j & 127;
    const bool gate_th = (j < 256);
    const int  b_g   = s ? b_s1 : b_s0;
    const int  len_g = s ? len1 : len0;

    for (int t = 0; t < maxlen; ++t) {
        // prefetch xp gate inputs (dead-read safe: guarded by t<len below)
        float xz = 0.f, xr = 0.f, xh = 0.f;
        if (gate_th) {
            const float* xpt = xp + (size_t)t * ROW3 + (size_t)b_g * ND3;
            xz = xpt[d];
            xr = xpt[128 + d];
            xh = xpt[256 + d];
        }
        // rp[s][j] = sum_k h[s][k] * U[k][j] + b_rec[j]
        ull acc0 = pk2(brec, 0.f);
        ull acc1 = pk2(brec, 0.f);
#pragma unroll
        for (int q = 0; q < 32; ++q) {
            ull u0 = u2[2 * q], u1 = u2[2 * q + 1];
            ulonglong2 h0 = *(const ulonglong2*)&hsm[0][4 * q];
            ulonglong2 h1 = *(const ulonglong2*)&hsm[1][4 * q];
            ffma2(acc0, u0, h0.x);
            ffma2(acc0, u1, h0.y);
            ffma2(acc1, u0, h1.x);
            ffma2(acc1, u1, h1.y);
        }
        { float2 f = upk2(acc0); rps[0][j] = f.x + f.y; }
        { float2 f = upk2(acc1); rps[1][j] = f.x + f.y; }
        __syncthreads();

        if (gate_th) {
            float h_old = hsm[s][d];
            float hn = h_old;
            if (t < len_g) {
                float zg = sigm(xz + rps[s][d]);
                float rg = sigm(xr + rps[s][128 + d]);
                float hh = tanhf(xh + rg * rps[s][256 + d]);
                hn = zg * h_old + (1.f - zg) * hh;
            }
            hsm[s][d] = hn;
            st[(size_t)b_g * TD + (size_t)t * DDIM + d] = hn;
        }
        __syncthreads();
    }
    // tail fill: t in [maxlen, T) carries the final state
    const int tail = TSEQ - maxlen;
    for (int idx = j; idx < tail * 256; idx += 384) {
        int dd = idx & 127;
        int ss = (idx >> 7) & 1;
        int tt = idx >> 8;
        int bb = ss ? b_s1 : b_s0;
        st[(size_t)bb * TD + (size_t)(maxlen + tt) * DDIM + dd] = hsm[ss][dd];
    }
}

// ============================================================================
// Kernel 3: fused attention epilogue, one block per batch sample (128 threads).
// ============================================================================
__global__ void __launch_bounds__(128, 2) k_attn(
    const float* __restrict__ x,
    const float* __restrict__ W_alpha, const float* __restrict__ b_alpha,
    const float* __restrict__ W_beta,  const float* __restrict__ b_beta,
    float* __restrict__ out)
{
    __shared__ float e_s[TSEQ];
    __shared__ float red[4];
    __shared__ float scal[2];
    __shared__ __align__(16) float hwin[8][DDIM];
    __shared__ float xwin[8][DDIM];

    const int b    = blockIdx.x;
    const int tid  = threadIdx.x;
    const int lane = tid & 31, w = tid >> 5;

    // ---- phase 1: e[t] = g[b][t] . W_alpha + b_alpha (warp per t) ----
    float4 wa = *(const float4*)&W_alpha[lane * 4];
    const float b_a = b_alpha[0];
    const float* gbase = g_g + (size_t)b * TD;
    for (int tt = 0; tt < 128; ++tt) {
        int t = tt * 4 + w;
        float4 gv = *(const float4*)&gbase[(size_t)t * DDIM + lane * 4];
        float sum = gv.x * wa.x + gv.y * wa.y + gv.z * wa.z + gv.w * wa.w;
#pragma unroll
        for (int o = 16; o > 0; o >>= 1) sum += __shfl_xor_sync(0xffffffffu, sum, o);
        if (lane == 0) e_s[t] = sum + b_a;
    }
    __syncthreads();

    // ---- softmax over t (unnormalized exp; divide once at the end) ----
    float m = -1e30f;
    for (int i = tid; i < TSEQ; i += 128) m = fmaxf(m, e_s[i]);
#pragma unroll
    for (int o = 16; o > 0; o >>= 1) m = fmaxf(m, __shfl_xor_sync(0xffffffffu, m, o));
    if (lane == 0) red[w] = m;
    __syncthreads();
    if (tid == 0) scal[0] = fmaxf(fmaxf(red[0], red[1]), fmaxf(red[2], red[3]));
    __syncthreads();
    const float M = scal[0];
    float ss = 0.f;
    for (int i = tid; i < TSEQ; i += 128) { float p = __expf(e_s[i] - M); e_s[i] = p; ss += p; }
#pragma unroll
    for (int o = 16; o > 0; o >>= 1) ss += __shfl_xor_sync(0xffffffffu, ss, o);
    if (lane == 0) red[w] = ss;
    __syncthreads();
    if (tid == 0) scal[1] = red[0] + red[1] + red[2] + red[3];
    __syncthreads();
    const float Sinv = 1.f / scal[1];

    // ---- phase 2: beta GEMV with W_beta column in registers (f32x2 pairs) ----
    ull wb2[64];
#pragma unroll
    for (int kp = 0; kp < 64; ++kp)
        wb2[kp] = pk2(W_beta[(size_t)(2 * kp) * DDIM + tid],
                      W_beta[(size_t)(2 * kp + 1) * DDIM + tid]);
    const float bb = b_beta[tid];
    const float* hbase = g_h + (size_t)b * TD;
    const float* xbase = x   + (size_t)b * TD;
    float acc = 0.f;

    for (int tw = 0; tw < TSEQ; tw += 8) {
        __syncthreads();
#pragma unroll
        for (int l = 0; l < 8; ++l) {
            int idx = tid + l * 128;
            int tt = idx >> 7, k = idx & 127;
            hwin[tt][k] = hbase[(size_t)(tw + tt) * DDIM + k];
            xwin[tt][k] = xbase[(size_t)(tw + tt) * DDIM + k];
        }
        __syncthreads();
#pragma unroll
        for (int tt = 0; tt < 8; ++tt) {
            ull a2 = 0ull;
#pragma unroll
            for (int q = 0; q < 32; ++q) {
                ulonglong2 hv = *(const ulonglong2*)&hwin[tt][4 * q];
                ffma2(a2, wb2[2 * q],     hv.x);
                ffma2(a2, wb2[2 * q + 1], hv.y);
            }
            float2 f = upk2(a2);
            float beta = tanhf(f.x + f.y + bb);
            acc += e_s[tw + tt] * beta * xwin[tt][tid];
        }
    }
    out[(size_t)b * DDIM + tid] = acc * Sinv;
}

// ============================================================================
extern "C" void kernel_launch(void* const* d_in, const int* in_sizes, int n_in,
                              void* d_out, int out_size)
{
    const float* x       = (const float*)d_in[0];
    const int*   lengths = (const int*)  d_in[1];
    const float* Wa      = (const float*)d_in[2];
    const float* Ua      = (const float*)d_in[3];
    const float* ba_in   = (const float*)d_in[4];
    const float* ba_rec  = (const float*)d_in[5];
    const float* Wb      = (const float*)d_in[6];
    const float* Ub      = (const float*)d_in[7];
    const float* bb_in   = (const float*)d_in[8];
    const float* bb_rec  = (const float*)d_in[9];
    const float* W_alpha = (const float*)d_in[10];
    const float* b_alpha = (const float*)d_in[11];
    const float* W_beta  = (const float*)d_in[12];
    const float* b_beta  = (const float*)d_in[13];
    float* out = (float*)d_out;

    k_sort<<<1, BATCH>>>(lengths);
    k_xp  <<<dim3(2048, 6, 2), 256>>>(x, lengths, Wa, ba_in, Wb, bb_in);
    k_gru <<<256, 384>>>(lengths, Ua, ba_rec, Ub, bb_rec);
    k_attn<<<256, 128>>>(x, W_alpha, b_alpha, W_beta, b_beta, out);
    (void)in_sizes; (void)n_in; (void)out_size;
}

// round 7
// speedup vs baseline: 1.7125x; 1.0200x over previous
#include <cuda_runtime.h>
#include <cuda_bf16.h>
#include <cstdint>

// Problem dims (fixed)
#define BATCH 256
#define TSEQ  512
#define DDIM  128
#define ND3   384   // 3*D
#define NC    768   // combined output cols (Wa | Wb)
#define TD    65536 // TSEQ*DDIM (one sample of states)

// ---------------- scratch (static device arrays; no allocations) ----------------
__device__ float g_xpc[(size_t)BATCH * TSEQ * NC];  // [b][tau][768] natural-order proj
__device__ float g_g[(size_t)BATCH * TSEQ * DDIM];  // GRU a states [b][t][d]
__device__ float g_h[(size_t)BATCH * TSEQ * DDIM];  // GRU b states [b][t][d]
__device__ int   g_perm[BATCH];                     // descending-length permutation

typedef unsigned long long ull;

__device__ __forceinline__ void ffma2(ull &d, ull a, ull b) {
    asm("fma.rn.f32x2 %0, %1, %2, %0;" : "+l"(d) : "l"(a), "l"(b));
}
__device__ __forceinline__ ull pk2(float lo, float hi) {
    ull r; asm("mov.b64 %0, {%1,%2};" : "=l"(r) : "f"(lo), "f"(hi)); return r;
}
__device__ __forceinline__ float2 upk2(ull v) {
    float lo, hi; asm("mov.b64 {%0,%1}, %2;" : "=f"(lo), "=f"(hi) : "l"(v));
    return make_float2(lo, hi);
}
__device__ __forceinline__ float sigm(float v) { return 1.f / (1.f + __expf(-v)); }

// ============================================================================
// Kernel 0: descending rank-sort of lengths -> g_perm (O(B^2), one block)
// ============================================================================
__global__ void __launch_bounds__(BATCH) k_sort(const int* __restrict__ lengths)
{
    __shared__ int ls[BATCH];
    const int i = threadIdx.x;
    ls[i] = lengths[i];
    __syncthreads();
    const int li = ls[i];
    int r = 0;
#pragma unroll 8
    for (int j = 0; j < BATCH; ++j) {
        int lj = ls[j];
        r += (lj > li) || (lj == li && j < i);
    }
    g_perm[r] = i;
}

// ============================================================================
// Kernel 1: natural-order projection  g_xpc[b][tau][c] = x[b][tau] @ (Wa|Wb) + bias
// 64 tau x 64 c tiles; K=128 in two 64-chunks; A and B both k-paired (float2)
// in smem; warp remapped to 8x4 lanes for conflict-free LDS.128.
// Tiles with tau0 >= len are skipped (rows tau >= len are never read by k_gru).
// grid (2048, 12): x -> (b, tau-tile), y -> 64-col tile of the 768 combined cols
// ============================================================================
__global__ void __launch_bounds__(256) k_xp(
    const float* __restrict__ x, const int* __restrict__ lengths,
    const float* __restrict__ Wa, const float* __restrict__ ba,
    const float* __restrict__ Wb, const float* __restrict__ bb)
{
    const int rt   = blockIdx.x;
    const int b    = rt >> 3;
    const int tau0 = (rt & 7) << 6;
    const int len  = lengths[b];
    if (tau0 >= len) return;            // dead tile

    __shared__ __align__(16) float2 As2[32][66]; // As2[kp][t] = {A[t][2kp],A[t][2kp+1]}
    __shared__ __align__(16) float2 Bs2[32][66]; // Bs2[kp][c] = {W[2kp][c],W[2kp+1][c]}

    const int c0 = blockIdx.y << 6;     // 0..704
    const float* W    = (c0 < ND3) ? Wa : Wb;
    const float* bias = (c0 < ND3) ? ba : bb;
    const int cw = (c0 < ND3) ? c0 : (c0 - ND3);

    const int tid  = threadIdx.x;
    const int w    = tid >> 5, lane = tid & 31;
    const int txp  = ((w & 1) << 3) + (lane & 7);   // 0..15  (col group)
    const int typ  = ((w >> 1) << 2) + (lane >> 3); // 0..15  (row group)

    ull acc[4][4];
#pragma unroll
    for (int i = 0; i < 4; i++)
#pragma unroll
        for (int j = 0; j < 4; j++) acc[i][j] = 0ull;

    for (int kc = 0; kc < 2; ++kc) {
        __syncthreads();
        // A chunk: rows tau0..tau0+63, k = kc*64..+63 (coalesced, no masking)
#pragma unroll
        for (int l = 0; l < 16; ++l) {
            int idx = tid + l * 256;
            int tt = idx >> 6, kk = idx & 63;
            float v = x[((size_t)b * TSEQ + tau0 + tt) * DDIM + kc * 64 + kk];
            ((float*)&As2[kk >> 1][tt])[kk & 1] = v;
        }
        // B chunk
#pragma unroll
        for (int l = 0; l < 16; ++l) {
            int idx = tid + l * 256;
            int kk = idx >> 6, jj = idx & 63;
            float wv = W[(size_t)(kc * 64 + kk) * ND3 + cw + jj];
            ((float*)&Bs2[kk >> 1][jj])[kk & 1] = wv;
        }
        __syncthreads();
#pragma unroll
        for (int q = 0; q < 32; ++q) {
            ulonglong2 a0 = *(const ulonglong2*)&As2[q][4 * typ];
            ulonglong2 a1 = *(const ulonglong2*)&As2[q][4 * typ + 2];
            ulonglong2 b0 = *(const ulonglong2*)&Bs2[q][4 * txp];
            ulonglong2 b1 = *(const ulonglong2*)&Bs2[q][4 * txp + 2];
            ull av[4] = { a0.x, a0.y, a1.x, a1.y };
            ull bv[4] = { b0.x, b0.y, b1.x, b1.y };
#pragma unroll
            for (int i = 0; i < 4; i++)
#pragma unroll
                for (int j = 0; j < 4; j++)
                    ffma2(acc[i][j], av[i], bv[j]);
        }
    }
    // write float4 rows: [b][tau][c0 + 4*txp .. +3]
#pragma unroll
    for (int i = 0; i < 4; i++) {
        int tau = tau0 + 4 * typ + i;
        float4 o;
        float* po = (float*)&o;
#pragma unroll
        for (int j = 0; j < 4; j++) {
            float2 f = upk2(acc[i][j]);
            po[j] = f.x + f.y + bias[cw + 4 * txp + j];
        }
        *(float4*)&g_xpc[((size_t)b * TSEQ + tau) * NC + c0 + 4 * txp] = o;
    }
}

// ============================================================================
// Kernel 2: masked GRU recurrence. 148 persistent blocks = 2 GRUs x 74 slots.
// Slot s runs sorted pair s, then pair 147-s (if valid) -> snake balance,
// single wave. 384 threads; thread j owns U column j as 64 f32x2 pairs.
// xp is read in natural order at row (len-1-t).
// ============================================================================
__global__ void __launch_bounds__(384, 1) k_gru(
    const int*   __restrict__ lengths,
    const float* __restrict__ Ua, const float* __restrict__ ba_rec,
    const float* __restrict__ Ub, const float* __restrict__ bb_rec)
{
    __shared__ __align__(16) float hsm[2][DDIM];
    __shared__ float rps[2][ND3];

    const int gru  = (blockIdx.x >= 74) ? 1 : 0;
    const int slot = blockIdx.x - gru * 74;
    const int j    = threadIdx.x;

    const float* U   = gru ? Ub     : Ua;
    const float* brp = gru ? bb_rec : ba_rec;
    float*       st  = gru ? g_h    : g_g;
    const int    coff = gru * ND3;

    ull u2[64];
#pragma unroll
    for (int kp = 0; kp < 64; ++kp)
        u2[kp] = pk2(U[(size_t)(2 * kp) * ND3 + j], U[(size_t)(2 * kp + 1) * ND3 + j]);
    const float brec = brp[j];

    const int s  = (j >> 7) & 1;   // gate sample within pair
    const int d  = j & 127;
    const bool gate_th = (j < 256);

    int plist[2];
    int np = 1;
    plist[0] = slot;
    if (147 - slot < 128) { plist[1] = 147 - slot; np = 2; }

    for (int pi = 0; pi < np; ++pi) {
        const int pr   = plist[pi];
        const int b_s0 = g_perm[2 * pr];
        const int b_s1 = g_perm[2 * pr + 1];
        const int len0 = lengths[b_s0];
        const int len1 = lengths[b_s1];
        const int maxlen = max(len0, len1);
        const int b_g   = s ? b_s1 : b_s0;
        const int len_g = s ? len1 : len0;

        for (int idx = j; idx < 2 * DDIM; idx += 384) ((float*)hsm)[idx] = 0.f;
        __syncthreads();

        for (int t = 0; t < maxlen; ++t) {
            // prefetch gate inputs from natural-order xp at row len_g-1-t
            float xz = 0.f, xr = 0.f, xh = 0.f;
            if (gate_th && t < len_g) {
                const float* xpt = g_xpc + ((size_t)b_g * TSEQ + (len_g - 1 - t)) * NC + coff;
                xz = xpt[d];
                xr = xpt[128 + d];
                xh = xpt[256 + d];
            }
            // rp[s][j] = h[s] . U[:,j] + b_rec[j]
            ull acc0 = pk2(brec, 0.f);
            ull acc1 = pk2(brec, 0.f);
#pragma unroll
            for (int q = 0; q < 32; ++q) {
                ull u0 = u2[2 * q], u1 = u2[2 * q + 1];
                ulonglong2 h0 = *(const ulonglong2*)&hsm[0][4 * q];
                ulonglong2 h1 = *(const ulonglong2*)&hsm[1][4 * q];
                ffma2(acc0, u0, h0.x);
                ffma2(acc0, u1, h0.y);
                ffma2(acc1, u0, h1.x);
                ffma2(acc1, u1, h1.y);
            }
            { float2 f = upk2(acc0); rps[0][j] = f.x + f.y; }
            { float2 f = upk2(acc1); rps[1][j] = f.x + f.y; }
            __syncthreads();

            if (gate_th) {
                float h_old = hsm[s][d];
                float hn = h_old;
                if (t < len_g) {
                    float zg = sigm(xz + rps[s][d]);
                    float rg = sigm(xr + rps[s][128 + d]);
                    float hh = tanhf(xh + rg * rps[s][256 + d]);
                    hn = zg * h_old + (1.f - zg) * hh;
                }
                hsm[s][d] = hn;
                st[(size_t)b_g * TD + (size_t)t * DDIM + d] = hn;
            }
            __syncthreads();
        }
        // tail fill: t in [maxlen, T) carries the final state
        const int tail = TSEQ - maxlen;
        for (int idx = j; idx < tail * 256; idx += 384) {
            int dd = idx & 127;
            int ss = (idx >> 7) & 1;
            int tt = idx >> 8;
            int bb = ss ? b_s1 : b_s0;
            st[(size_t)bb * TD + (size_t)(maxlen + tt) * DDIM + dd] = hsm[ss][dd];
        }
        __syncthreads();
    }
}

// ============================================================================
// Kernel 3: fused attention epilogue. One block / sample, 256 threads:
// two 128-thread groups split the time axis in phase 2; partials combined.
// ============================================================================
__global__ void __launch_bounds__(256, 1) k_attn(
    const float* __restrict__ x,
    const float* __restrict__ W_alpha, const float* __restrict__ b_alpha,
    const float* __restrict__ W_beta,  const float* __restrict__ b_beta,
    float* __restrict__ out)
{
    __shared__ float e_s[TSEQ];
    __shared__ float red[8];
    __shared__ float scal[2];
    __shared__ __align__(16) float hwin[2][8][DDIM];
    __shared__ float xwin[2][8][DDIM];
    __shared__ float pacc[DDIM];

    const int b    = blockIdx.x;
    const int tid  = threadIdx.x;
    const int lane = tid & 31, w = tid >> 5;

    // ---- phase 1: e[t] = g[b][t] . W_alpha + b_alpha (warp per t, 8 warps) ----
    float4 wa = *(const float4*)&W_alpha[lane * 4];
    const float b_a = b_alpha[0];
    const float* gbase = g_g + (size_t)b * TD;
    for (int tt = 0; tt < 64; ++tt) {
        int t = tt * 8 + w;
        float4 gv = *(const float4*)&gbase[(size_t)t * DDIM + lane * 4];
        float sum = gv.x * wa.x + gv.y * wa.y + gv.z * wa.z + gv.w * wa.w;
#pragma unroll
        for (int o = 16; o > 0; o >>= 1) sum += __shfl_xor_sync(0xffffffffu, sum, o);
        if (lane == 0) e_s[t] = sum + b_a;
    }
    __syncthreads();

    // ---- softmax over t (unnormalized exp; divide once at the end) ----
    float m = -1e30f;
    for (int i = tid; i < TSEQ; i += 256) m = fmaxf(m, e_s[i]);
#pragma unroll
    for (int o = 16; o > 0; o >>= 1) m = fmaxf(m, __shfl_xor_sync(0xffffffffu, m, o));
    if (lane == 0) red[w] = m;
    __syncthreads();
    if (tid == 0) {
        float mm = red[0];
#pragma unroll
        for (int i = 1; i < 8; ++i) mm = fmaxf(mm, red[i]);
        scal[0] = mm;
    }
    __syncthreads();
    const float M = scal[0];
    float ss = 0.f;
    for (int i = tid; i < TSEQ; i += 256) { float p = __expf(e_s[i] - M); e_s[i] = p; ss += p; }
#pragma unroll
    for (int o = 16; o > 0; o >>= 1) ss += __shfl_xor_sync(0xffffffffu, ss, o);
    if (lane == 0) red[w] = ss;
    __syncthreads();
    if (tid == 0) {
        float t2 = 0.f;
#pragma unroll
        for (int i = 0; i < 8; ++i) t2 += red[i];
        scal[1] = t2;
    }
    __syncthreads();
    const float Sinv = 1.f / scal[1];

    // ---- phase 2: beta GEMV, time axis split across two 128-thread groups ----
    const int grp = tid >> 7;
    const int dd  = tid & 127;

    ull wb2[64];
#pragma unroll
    for (int kp = 0; kp < 64; ++kp)
        wb2[kp] = pk2(W_beta[(size_t)(2 * kp) * DDIM + dd],
                      W_beta[(size_t)(2 * kp + 1) * DDIM + dd]);
    const float bbv = b_beta[dd];
    const float* hbase = g_h + (size_t)b * TD;
    const float* xbase = x   + (size_t)b * TD;
    const int tws = grp * 256;
    float acc = 0.f;

    for (int tw = 0; tw < 256; tw += 8) {
        __syncthreads();
#pragma unroll
        for (int l = 0; l < 8; ++l) {
            int idx = dd + l * 128;
            int tt = idx >> 7, k = idx & 127;
            hwin[grp][tt][k] = hbase[(size_t)(tws + tw + tt) * DDIM + k];
            xwin[grp][tt][k] = xbase[(size_t)(tws + tw + tt) * DDIM + k];
        }
        __syncthreads();
#pragma unroll
        for (int tt = 0; tt < 8; ++tt) {
            ull a2 = 0ull;
#pragma unroll
            for (int q = 0; q < 32; ++q) {
                ulonglong2 hv = *(const ulonglong2*)&hwin[grp][tt][4 * q];
                ffma2(a2, wb2[2 * q],     hv.x);
                ffma2(a2, wb2[2 * q + 1], hv.y);
            }
            float2 f = upk2(a2);
            float beta = tanhf(f.x + f.y + bbv);
            acc += e_s[tws + tw + tt] * beta * xwin[grp][tt][dd];
        }
    }
    if (grp == 1) pacc[dd] = acc;
    __syncthreads();
    if (grp == 0) out[(size_t)b * DDIM + dd] = (acc + pacc[dd]) * Sinv;
}

// ============================================================================
extern "C" void kernel_launch(void* const* d_in, const int* in_sizes, int n_in,
                              void* d_out, int out_size)
{
    const float* x       = (const float*)d_in[0];
    const int*   lengths = (const int*)  d_in[1];
    const float* Wa      = (const float*)d_in[2];
    const float* Ua      = (const float*)d_in[3];
    const float* ba_in   = (const float*)d_in[4];
    const float* ba_rec  = (const float*)d_in[5];
    const float* Wb      = (const float*)d_in[6];
    const float* Ub      = (const float*)d_in[7];
    const float* bb_in   = (const float*)d_in[8];
    const float* bb_rec  = (const float*)d_in[9];
    const float* W_alpha = (const float*)d_in[10];
    const float* b_alpha = (const float*)d_in[11];
    const float* W_beta  = (const float*)d_in[12];
    const float* b_beta  = (const float*)d_in[13];
    float* out = (float*)d_out;

    k_sort<<<1, BATCH>>>(lengths);
    k_xp  <<<dim3(2048, 12), 256>>>(x, lengths, Wa, ba_in, Wb, bb_in);
    k_gru <<<148, 384>>>(lengths, Ua, ba_rec, Ub, bb_rec);
    k_attn<<<256, 256>>>(x, W_alpha, b_alpha, W_beta, b_beta, out);
    (void)in_sizes; (void)n_in; (void)out_size;
}